// round 8
// baseline (speedup 1.0000x reference)
#include <cuda_runtime.h>
#include <math.h>
#include <stdint.h>

#define Bq  2
#define Sq  2048
#define Dq  1024
#define Hq  16
#define HDq 64

__device__ float g_qkv[(size_t)Bq * Sq * 3 * Dq];   // tf32-rounded, head-interleaved q/k (v cols unused)
__device__ float g_vT[(size_t)Bq * Hq * HDq * Sq];  // tf32-rounded V, [b][h][d][s]
__device__ float g_vals[(size_t)Bq * Sq * Dq];      // tf32-rounded attn out
__device__ float g_xc[(size_t)Bq * Sq * Dq];        // tf32-rounded x
__device__ float g_wqkvc[(size_t)3 * Dq * Dq];      // tf32-rounded Wqkv
__device__ float g_woc[(size_t)Dq * Dq];            // tf32-rounded Wo

// ---------------------------------------------------------------------------
__device__ __forceinline__ uint32_t f2tf32(float x) {
    uint32_t r;
    asm("cvt.rna.tf32.f32 %0, %1;" : "=r"(r) : "f"(x));
    return r;
}
__device__ __forceinline__ float roundtf(float x) {
    return __uint_as_float(f2tf32(x));
}
__device__ __forceinline__ uint32_t smem_u32(const void* p) {
    return (uint32_t)__cvta_generic_to_shared(p);
}

__device__ __forceinline__ void mma_tf32(float c[4],
                                         uint32_t a0, uint32_t a1, uint32_t a2, uint32_t a3,
                                         uint32_t b0, uint32_t b1) {
    asm volatile(
        "mma.sync.aligned.m16n8k8.row.col.f32.tf32.tf32.f32 "
        "{%0,%1,%2,%3}, {%4,%5,%6,%7}, {%8,%9}, {%0,%1,%2,%3};"
        : "+f"(c[0]), "+f"(c[1]), "+f"(c[2]), "+f"(c[3])
        : "r"(a0), "r"(a1), "r"(a2), "r"(a3), "r"(b0), "r"(b1));
}

// ldmatrix x4 on tf32 data (viewed as b16); mapping verified against
// mma.m16n8k8 tf32 fragment layout.
__device__ __forceinline__ void ldsm_x4(uint32_t r[4], uint32_t addr) {
    asm volatile("ldmatrix.sync.aligned.m8n8.x4.shared.b16 {%0,%1,%2,%3}, [%4];"
                 : "=r"(r[0]), "=r"(r[1]), "=r"(r[2]), "=r"(r[3]) : "r"(addr));
}

__device__ __forceinline__ void cp16(uint32_t dst, const float* src) {
    asm volatile("cp.async.cg.shared.global [%0], [%1], 16;" :: "r"(dst), "l"(src));
}
__device__ __forceinline__ void cp_commit() {
    asm volatile("cp.async.commit_group;");
}
template <int N>
__device__ __forceinline__ void cp_wait() {
    asm volatile("cp.async.wait_group %0;" :: "n"(N));
}

// ---------------------------------------------------------------------------
__global__ void __launch_bounds__(256)
round_tf32_kernel(const float* __restrict__ src, float* __restrict__ dst, int n)
{
    const int i = (blockIdx.x * 256 + threadIdx.x) * 4;
    if (i < n) {
        float4 v = *(const float4*)(src + i);
        v.x = roundtf(v.x); v.y = roundtf(v.y);
        v.z = roundtf(v.z); v.w = roundtf(v.w);
        *(float4*)(dst + i) = v;
    }
}

// ---------------------------------------------------------------------------
// tf32 GEMM: C[M,N] = A[M,K] @ W[N,K]^T + bias[N]
// BM=BN=128, BK=32, 256 thr (8 warps 2x4, warp 64x32), 2-stage cp.async,
// fragments via ldmatrix. VSPLIT (QKV projection): per 8-column group,
// role = (c%192)/64; q/k -> C rounded; v -> transposed into vT[b][h][d][s].
// ---------------------------------------------------------------------------
template <bool ROUND, bool VSPLIT>
__global__ void __launch_bounds__(256, 2)
gemm_ldsm(int M, int N, int K,
          const float* __restrict__ A,
          const float* __restrict__ W,
          const float* __restrict__ bias,
          float* __restrict__ C,
          float* __restrict__ vT)
{
    constexpr int PITCH = 36;              // 144B rows: 16B-aligned, odd x16B -> LDSM conflict-free
    constexpr int TILE_W = 128 * PITCH;
    extern __shared__ float smf[];
    const uint32_t sbase = smem_u32(smf);
    const uint32_t ABASE = sbase;
    const uint32_t WBASE = sbase + 2u * TILE_W * 4u;

    const int tid  = threadIdx.x;
    const int lane = tid & 31;
    const int w    = tid >> 5;
    const int wr   = w >> 2;
    const int wc   = w & 3;
    const int m0   = blockIdx.y * 128;
    const int n0   = blockIdx.x * 128;
    const int g    = lane >> 2;
    const int tq   = lane & 3;

    const int lrow = tid >> 1;
    const int lcb  = (tid & 1) * 16;
    const float* Ap = A + (size_t)(m0 + lrow) * K + lcb;
    const float* Wp = W + (size_t)(n0 + lrow) * K + lcb;
    const uint32_t lso = (uint32_t)(lrow * PITCH + lcb) * 4;

#define G_ISSUE(stg, ko)                                            \
    do {                                                            \
        const uint32_t ab = ABASE + (uint32_t)(stg) * TILE_W * 4 + lso; \
        const uint32_t wb = WBASE + (uint32_t)(stg) * TILE_W * 4 + lso; \
        _Pragma("unroll")                                           \
        for (int j = 0; j < 4; j++) {                               \
            cp16(ab + j * 16, Ap + (ko) + j * 4);                   \
            cp16(wb + j * 16, Wp + (ko) + j * 4);                   \
        }                                                           \
        cp_commit();                                                \
    } while (0)

    const int rA = (lane & 7) + (lane & 8);
    const int cA = (lane >> 4) << 2;
    const int rB = (lane & 7) + ((lane >> 4) << 3);
    const int cB = ((lane >> 3) & 1) << 2;

    float acc[4][4][4];
#pragma unroll
    for (int i = 0; i < 4; i++)
#pragma unroll
        for (int j = 0; j < 4; j++)
#pragma unroll
            for (int e = 0; e < 4; e++) acc[i][j][e] = 0.0f;

    const int nIter = K / 32;
    G_ISSUE(0, 0);

    for (int it = 0; it < nIter; it++) {
        cp_wait<0>();
        __syncthreads();
        if (it + 1 < nIter) G_ISSUE((it + 1) & 1, (it + 1) * 32);

        const uint32_t ab = ABASE + (uint32_t)(it & 1) * TILE_W * 4;
        const uint32_t wb = WBASE + (uint32_t)(it & 1) * TILE_W * 4;

#pragma unroll
        for (int ks = 0; ks < 4; ks++) {
            const int kk = ks * 8;
            uint32_t a[4][4];
#pragma unroll
            for (int mi = 0; mi < 4; mi++)
                ldsm_x4(a[mi], ab + (uint32_t)((wr * 64 + mi * 16 + rA) * PITCH + kk + cA) * 4);
            uint32_t bt[2][4];
#pragma unroll
            for (int nti = 0; nti < 2; nti++)
                ldsm_x4(bt[nti], wb + (uint32_t)((wc * 32 + nti * 16 + rB) * PITCH + kk + cB) * 4);
#pragma unroll
            for (int mi = 0; mi < 4; mi++)
#pragma unroll
                for (int ni = 0; ni < 4; ni++)
                    mma_tf32(acc[mi][ni], a[mi][0], a[mi][1], a[mi][2], a[mi][3],
                             bt[ni >> 1][(ni & 1) * 2], bt[ni >> 1][(ni & 1) * 2 + 1]);
        }
    }

#pragma unroll
    for (int mi = 0; mi < 4; mi++) {
        const int r0 = m0 + wr * 64 + mi * 16 + g;
#pragma unroll
        for (int ni = 0; ni < 4; ni++) {
            const int c = n0 + wc * 32 + ni * 8 + 2 * tq;
            const float b0v = bias[c], b1v = bias[c + 1];
            // role of this 8-col group (groups are 8-aligned, never cross a 64-boundary)
            if (VSPLIT && ((c % 192) >> 6) == 2) {
                // V feature: store transposed into vT[b][h][d][s]
                const int hh = c / 192;
                const int dd = (c % 192) - 128;
#pragma unroll
                for (int e = 0; e < 4; e++) {
                    const int row = r0 + (e >> 1) * 8;
                    const int bb = row >> 11, ss = row & 2047;
                    const float bv = (e & 1) ? b1v : b0v;
                    vT[(size_t)((bb * Hq + hh) * HDq + dd + (e & 1)) * Sq + ss] =
                        roundtf(acc[mi][ni][e] + bv);
                }
            } else {
                float2 o0, o1;
                if (ROUND) {
                    o0 = make_float2(roundtf(acc[mi][ni][0] + b0v), roundtf(acc[mi][ni][1] + b1v));
                    o1 = make_float2(roundtf(acc[mi][ni][2] + b0v), roundtf(acc[mi][ni][3] + b1v));
                } else {
                    o0 = make_float2(acc[mi][ni][0] + b0v, acc[mi][ni][1] + b1v);
                    o1 = make_float2(acc[mi][ni][2] + b0v, acc[mi][ni][3] + b1v);
                }
                *(float2*)(C + (size_t)r0 * N + c)       = o0;
                *(float2*)(C + (size_t)(r0 + 8) * N + c) = o1;
            }
        }
    }
#undef G_ISSUE
}

// ---------------------------------------------------------------------------
// Flash attention tf32: 256 threads, 128 q rows/block, 64-key tiles.
// Q frags register-resident (LDSM once). K from g_qkv [key][d] (head-
// interleaved); V from g_vT [d][key]; cp.async 2-stage; all frags via LDSM.
// ---------------------------------------------------------------------------
#define FP 68
#define KV_STAGE_W (64 * FP)

__global__ void __launch_bounds__(256)
flash_ldsm(const float* __restrict__ qkv,
           const float* __restrict__ vT,
           const float* __restrict__ mask,
           float* __restrict__ out)
{
    extern __shared__ float smf[];
    const uint32_t sbase = smem_u32(smf);
    const uint32_t QBASE = sbase;
    const uint32_t KBASE = sbase + (uint32_t)(128 * FP) * 4;
    const uint32_t VBASE = KBASE + (uint32_t)(2 * KV_STAGE_W) * 4;

    const int tid  = threadIdx.x;
    const int lane = tid & 31;
    const int w    = tid >> 5;
    const int g    = lane >> 2;
    const int tq   = lane & 3;

    const int q0 = blockIdx.x * 128;
    const int h  = blockIdx.y;
    const int b  = blockIdx.z;
    const float scale = 0.125f;

    const float* base  = qkv + (size_t)b * Sq * (3 * Dq) + (size_t)h * (3 * HDq);
    const float* vbase = vT + (size_t)(b * Hq + h) * HDq * Sq;

    const int rA = (lane & 7) + (lane & 8);
    const int cA = (lane >> 4) << 2;
    const int rB = (lane & 7) + ((lane >> 4) << 3);
    const int cB = ((lane >> 3) & 1) << 2;

    const int ldr = tid >> 2;
    const int ldc = (tid & 3) * 16;
    const float* Kp = base + 64 + (size_t)ldr * (3 * Dq) + ldc;
    const float* Vp = vbase + (size_t)ldr * Sq + ldc;
    const uint32_t soff = (uint32_t)(ldr * FP + ldc) * 4;

#define F_ISSUE(stg, kt)                                                  \
    do {                                                                  \
        const uint32_t kb = KBASE + (uint32_t)(stg) * KV_STAGE_W * 4 + soff; \
        const uint32_t vb = VBASE + (uint32_t)(stg) * KV_STAGE_W * 4 + soff; \
        const size_t kgo = (size_t)(kt) * 64 * (3 * Dq);                  \
        const size_t vgo = (size_t)(kt) * 64;                             \
        _Pragma("unroll")                                                 \
        for (int j = 0; j < 4; j++) {                                     \
            cp16(kb + j * 16, Kp + kgo + j * 4);                          \
            cp16(vb + j * 16, Vp + vgo + j * 4);                          \
        }                                                                 \
        cp_commit();                                                      \
    } while (0)

    F_ISSUE(0, 0);

    {
        const int r  = tid >> 4;
        const int c4 = (tid & 15) << 2;
#pragma unroll
        for (int rr = 0; rr < 8; rr++) {
            const int row = r + rr * 16;
            float4 v = *(const float4*)(base + (size_t)(q0 + row) * (3 * Dq) + c4);
            *(float4*)(smf + row * FP + c4) = v;
        }
    }
    __syncthreads();

    uint32_t qa[8][4];
#pragma unroll
    for (int ks = 0; ks < 8; ks++)
        ldsm_x4(qa[ks], QBASE + (uint32_t)((w * 16 + rA) * FP + ks * 8 + cA) * 4);
    __syncthreads();

    float Oacc[8][4];
#pragma unroll
    for (int ni = 0; ni < 8; ni++)
#pragma unroll
        for (int e = 0; e < 4; e++) Oacc[ni][e] = 0.0f;
    float mrow0 = -INFINITY, mrow1 = -INFINITY;
    float lrow0 = 0.0f, lrow1 = 0.0f;

    const int r0 = w * 16 + g;
    const int r1 = r0 + 8;

    constexpr int NT = Sq / 64;
    for (int kt = 0; kt < NT; kt++) {
        const int k0t = kt * 64;

        cp_wait<0>();
        __syncthreads();
        if (kt + 1 < NT) F_ISSUE((kt + 1) & 1, kt + 1);

        const uint32_t kb = KBASE + (uint32_t)(kt & 1) * KV_STAGE_W * 4;
        const uint32_t vb = VBASE + (uint32_t)(kt & 1) * KV_STAGE_W * 4;

        float Sacc[8][4];
#pragma unroll
        for (int ni = 0; ni < 8; ni++)
#pragma unroll
            for (int e = 0; e < 4; e++) Sacc[ni][e] = 0.0f;

#pragma unroll
        for (int ks = 0; ks < 8; ks++) {
            const int kk = ks * 8;
            uint32_t kf[4][4];
#pragma unroll
            for (int nti = 0; nti < 4; nti++)
                ldsm_x4(kf[nti], kb + (uint32_t)((nti * 16 + rB) * FP + kk + cB) * 4);
#pragma unroll
            for (int ni = 0; ni < 8; ni++)
                mma_tf32(Sacc[ni], qa[ks][0], qa[ks][1], qa[ks][2], qa[ks][3],
                         kf[ni >> 1][(ni & 1) * 2], kf[ni >> 1][(ni & 1) * 2 + 1]);
        }

        float rmax0 = -INFINITY, rmax1 = -INFINITY;
#pragma unroll
        for (int ni = 0; ni < 8; ni++) {
            const int c = ni * 8 + 2 * tq;
            float2 mk0 = *(const float2*)(mask + (size_t)(q0 + r0) * Sq + k0t + c);
            float2 mk1 = *(const float2*)(mask + (size_t)(q0 + r1) * Sq + k0t + c);
            Sacc[ni][0] = Sacc[ni][0] * scale + mk0.x;
            Sacc[ni][1] = Sacc[ni][1] * scale + mk0.y;
            Sacc[ni][2] = Sacc[ni][2] * scale + mk1.x;
            Sacc[ni][3] = Sacc[ni][3] * scale + mk1.y;
            rmax0 = fmaxf(rmax0, fmaxf(Sacc[ni][0], Sacc[ni][1]));
            rmax1 = fmaxf(rmax1, fmaxf(Sacc[ni][2], Sacc[ni][3]));
        }
#pragma unroll
        for (int off = 1; off < 4; off <<= 1) {
            rmax0 = fmaxf(rmax0, __shfl_xor_sync(0xffffffffu, rmax0, off));
            rmax1 = fmaxf(rmax1, __shfl_xor_sync(0xffffffffu, rmax1, off));
        }
        const float mnew0 = fmaxf(mrow0, rmax0);
        const float mnew1 = fmaxf(mrow1, rmax1);
        const float alpha0 = __expf(mrow0 - mnew0);
        const float alpha1 = __expf(mrow1 - mnew1);
        float rs0 = 0.0f, rs1 = 0.0f;
#pragma unroll
        for (int ni = 0; ni < 8; ni++) {
            Sacc[ni][0] = __expf(Sacc[ni][0] - mnew0);
            Sacc[ni][1] = __expf(Sacc[ni][1] - mnew0);
            Sacc[ni][2] = __expf(Sacc[ni][2] - mnew1);
            Sacc[ni][3] = __expf(Sacc[ni][3] - mnew1);
            rs0 += Sacc[ni][0] + Sacc[ni][1];
            rs1 += Sacc[ni][2] + Sacc[ni][3];
        }
#pragma unroll
        for (int off = 1; off < 4; off <<= 1) {
            rs0 += __shfl_xor_sync(0xffffffffu, rs0, off);
            rs1 += __shfl_xor_sync(0xffffffffu, rs1, off);
        }
        lrow0 = lrow0 * alpha0 + rs0;
        lrow1 = lrow1 * alpha1 + rs1;
        mrow0 = mnew0;
        mrow1 = mnew1;
#pragma unroll
        for (int ni = 0; ni < 8; ni++) {
            Oacc[ni][0] *= alpha0; Oacc[ni][1] *= alpha0;
            Oacc[ni][2] *= alpha1; Oacc[ni][3] *= alpha1;
        }

        {
            uint32_t* Pu = (uint32_t*)smf;
            const int qr0 = w * 16 + g;
#pragma unroll
            for (int ni = 0; ni < 8; ni++) {
                const int c = ni * 8 + 2 * tq;
                uint2 s0 = make_uint2(f2tf32(Sacc[ni][0]), f2tf32(Sacc[ni][1]));
                uint2 s1 = make_uint2(f2tf32(Sacc[ni][2]), f2tf32(Sacc[ni][3]));
                *(uint2*)(Pu + (qr0)     * FP + c) = s0;
                *(uint2*)(Pu + (qr0 + 8) * FP + c) = s1;
            }
        }
        __syncwarp();

#pragma unroll
        for (int ks = 0; ks < 8; ks++) {
            const int kk = ks * 8;
            uint32_t pa[4];
            ldsm_x4(pa, QBASE + (uint32_t)((w * 16 + rA) * FP + kk + cA) * 4);
            uint32_t vf[4][4];
#pragma unroll
            for (int nti = 0; nti < 4; nti++)
                ldsm_x4(vf[nti], vb + (uint32_t)((nti * 16 + rB) * FP + kk + cB) * 4);
#pragma unroll
            for (int ni = 0; ni < 8; ni++)
                mma_tf32(Oacc[ni], pa[0], pa[1], pa[2], pa[3],
                         vf[ni >> 1][(ni & 1) * 2], vf[ni >> 1][(ni & 1) * 2 + 1]);
        }
    }

    const float inv0 = 1.0f / lrow0;
    const float inv1 = 1.0f / lrow1;
    float* obase = out + (size_t)b * Sq * Dq + (size_t)h * HDq;
#pragma unroll
    for (int ni = 0; ni < 8; ni++) {
        const int c = ni * 8 + 2 * tq;
        float2 o0 = make_float2(roundtf(Oacc[ni][0] * inv0), roundtf(Oacc[ni][1] * inv0));
        float2 o1 = make_float2(roundtf(Oacc[ni][2] * inv1), roundtf(Oacc[ni][3] * inv1));
        *(float2*)(obase + (size_t)(q0 + r0) * Dq + c) = o0;
        *(float2*)(obase + (size_t)(q0 + r1) * Dq + c) = o1;
    }
#undef F_ISSUE
}

// ---------------------------------------------------------------------------
extern "C" void kernel_launch(void* const* d_in, const int* in_sizes, int n_in,
                              void* d_out, int out_size)
{
    const float* x    = (const float*)d_in[0];
    const float* mask = (const float*)d_in[1];
    const float* Wqkv = (const float*)d_in[2];
    const float* bqkv = (const float*)d_in[3];
    const float* Wo   = (const float*)d_in[4];
    const float* bo   = (const float*)d_in[5];
    float* out = (float*)d_out;

    float *qkv, *vT, *vals, *xc, *wqkvc, *woc;
    cudaGetSymbolAddress((void**)&qkv,   g_qkv);
    cudaGetSymbolAddress((void**)&vT,    g_vT);
    cudaGetSymbolAddress((void**)&vals,  g_vals);
    cudaGetSymbolAddress((void**)&xc,    g_xc);
    cudaGetSymbolAddress((void**)&wqkvc, g_wqkvc);
    cudaGetSymbolAddress((void**)&woc,   g_woc);

    // 0) pre-round GEMM operands to tf32
    {
        const int nx = Bq * Sq * Dq;
        const int nq = 3 * Dq * Dq;
        const int no = Dq * Dq;
        round_tf32_kernel<<<nx / 1024, 256>>>(x, xc, nx);
        round_tf32_kernel<<<nq / 1024, 256>>>(Wqkv, wqkvc, nq);
        round_tf32_kernel<<<no / 1024, 256>>>(Wo, woc, no);
    }

    const int gemm_smem = 2 * 2 * 128 * 36 * (int)sizeof(float);   // 73728
    cudaFuncSetAttribute(gemm_ldsm<true, true>,
                         cudaFuncAttributeMaxDynamicSharedMemorySize, gemm_smem);
    cudaFuncSetAttribute(gemm_ldsm<false, false>,
                         cudaFuncAttributeMaxDynamicSharedMemorySize, gemm_smem);

    // 1) QKV projection: q/k cols -> g_qkv (rounded); v cols -> g_vT transposed
    {
        dim3 grid((3 * Dq) / 128, (Bq * Sq) / 128);
        gemm_ldsm<true, true><<<grid, 256, gemm_smem>>>(Bq * Sq, 3 * Dq, Dq,
                                                        xc, wqkvc, bqkv, qkv, vT);
    }

    // 2) Flash attention
    {
        const int smem = (128 * FP + 4 * KV_STAGE_W) * (int)sizeof(float);  // 104448
        cudaFuncSetAttribute(flash_ldsm,
                             cudaFuncAttributeMaxDynamicSharedMemorySize, smem);
        dim3 grid(Sq / 128, Hq, Bq);
        flash_ldsm<<<grid, 256, smem>>>(qkv, vT, mask, vals);
    }

    // 3) Output projection
    {
        dim3 grid(Dq / 128, (Bq * Sq) / 128);
        gemm_ldsm<false, false><<<grid, 256, gemm_smem>>>(Bq * Sq, Dq, Dq,
                                                          vals, woc, bo, out, vT);
    }
}

// round 9
// speedup vs baseline: 1.2769x; 1.2769x over previous
#include <cuda_runtime.h>
#include <math.h>
#include <stdint.h>

// Problem constants
#define Bq  2
#define Sq  2048
#define Dq  1024
#define Hq  16
#define HDq 64

__device__ float g_qkv[(size_t)Bq * Sq * 3 * Dq];   // (B,S,3D)
__device__ float g_vals[(size_t)Bq * Sq * Dq];      // (B,S,D)

// ---------------------------------------------------------------------------
// tf32 helpers
// ---------------------------------------------------------------------------
__device__ __forceinline__ uint32_t f2tf32(float x) {
    uint32_t r;
    asm("cvt.rna.tf32.f32 %0, %1;" : "=r"(r) : "f"(x));
    return r;
}

__device__ __forceinline__ void mma_tf32(float c[4],
                                         uint32_t a0, uint32_t a1, uint32_t a2, uint32_t a3,
                                         uint32_t b0, uint32_t b1) {
    asm volatile(
        "mma.sync.aligned.m16n8k8.row.col.f32.tf32.tf32.f32 "
        "{%0,%1,%2,%3}, {%4,%5,%6,%7}, {%8,%9}, {%0,%1,%2,%3};"
        : "+f"(c[0]), "+f"(c[1]), "+f"(c[2]), "+f"(c[3])
        : "r"(a0), "r"(a1), "r"(a2), "r"(a3), "r"(b0), "r"(b1));
}

// ---------------------------------------------------------------------------
// tf32 GEMM: C[M,N] = A[M,K] @ W[N,K]^T + bias[N]
// BM=128, BN=128, BK=32. 256 threads = 8 warps in 2x4; warp tile 64x32.
// (verbatim round-2 kernel — measured 210us QKV / 70us out-proj)
// ---------------------------------------------------------------------------
__global__ void __launch_bounds__(256)
gemm_tf32_nt_bias(int M, int N, int K,
                  const float* __restrict__ A,
                  const float* __restrict__ W,
                  const float* __restrict__ bias,
                  float* __restrict__ C)
{
    constexpr int BK = 32, PITCH = 36;
    __shared__ uint32_t As[128][PITCH];
    __shared__ uint32_t Ws[128][PITCH];

    const int tid  = threadIdx.x;
    const int lane = tid & 31;
    const int w    = tid >> 5;
    const int wr   = w >> 2;      // 0..1
    const int wc   = w & 3;       // 0..3
    const int m0   = blockIdx.y * 128;
    const int n0   = blockIdx.x * 128;

    const int g  = lane >> 2;     // groupID 0..7
    const int tq = lane & 3;      // threadID in quad 0..3

    float acc[4][4][4];
#pragma unroll
    for (int i = 0; i < 4; i++)
#pragma unroll
        for (int j = 0; j < 4; j++)
#pragma unroll
            for (int e = 0; e < 4; e++) acc[i][j][e] = 0.0f;

    const int lrow = tid >> 3;          // 0..31
    const int lc4  = (tid & 7) << 2;    // 0..28

    for (int k0 = 0; k0 < K; k0 += BK) {
#pragma unroll
        for (int rr = 0; rr < 4; rr++) {
            const int r = lrow + rr * 32;
            float4 av = *(const float4*)(A + (size_t)(m0 + r) * K + k0 + lc4);
            As[r][lc4 + 0] = f2tf32(av.x); As[r][lc4 + 1] = f2tf32(av.y);
            As[r][lc4 + 2] = f2tf32(av.z); As[r][lc4 + 3] = f2tf32(av.w);
            float4 wv = *(const float4*)(W + (size_t)(n0 + r) * K + k0 + lc4);
            Ws[r][lc4 + 0] = f2tf32(wv.x); Ws[r][lc4 + 1] = f2tf32(wv.y);
            Ws[r][lc4 + 2] = f2tf32(wv.z); Ws[r][lc4 + 3] = f2tf32(wv.w);
        }
        __syncthreads();

#pragma unroll
        for (int ks = 0; ks < 4; ks++) {
            const int kk = ks * 8;
            uint32_t af[4][4];
#pragma unroll
            for (int mi = 0; mi < 4; mi++) {
                const int rb = wr * 64 + mi * 16;
                af[mi][0] = As[rb + g    ][kk + tq    ];
                af[mi][1] = As[rb + g + 8][kk + tq    ];
                af[mi][2] = As[rb + g    ][kk + tq + 4];
                af[mi][3] = As[rb + g + 8][kk + tq + 4];
            }
            uint32_t bf[4][2];
#pragma unroll
            for (int ni = 0; ni < 4; ni++) {
                const int cb = wc * 32 + ni * 8;
                bf[ni][0] = Ws[cb + g][kk + tq    ];
                bf[ni][1] = Ws[cb + g][kk + tq + 4];
            }
#pragma unroll
            for (int mi = 0; mi < 4; mi++)
#pragma unroll
                for (int ni = 0; ni < 4; ni++)
                    mma_tf32(acc[mi][ni],
                             af[mi][0], af[mi][1], af[mi][2], af[mi][3],
                             bf[ni][0], bf[ni][1]);
        }
        __syncthreads();
    }

#pragma unroll
    for (int mi = 0; mi < 4; mi++) {
        const int r0 = m0 + wr * 64 + mi * 16 + g;
#pragma unroll
        for (int ni = 0; ni < 4; ni++) {
            const int c = n0 + wc * 32 + ni * 8 + 2 * tq;
            const float b0v = bias[c], b1v = bias[c + 1];
            float2 o0 = make_float2(acc[mi][ni][0] + b0v, acc[mi][ni][1] + b1v);
            float2 o1 = make_float2(acc[mi][ni][2] + b0v, acc[mi][ni][3] + b1v);
            *(float2*)(C + (size_t)r0 * N + c)       = o0;
            *(float2*)(C + (size_t)(r0 + 8) * N + c) = o1;
        }
    }
}

// ---------------------------------------------------------------------------
// Flash attention, tf32 tensor cores. Grid (S/64, H, B), 128 threads (4 warps).
// Identical structure to the proven round-2 kernel with ONE change:
// the P buffer is merged into the K buffer (P stash happens only after all
// warps finish reading K for S — guarded by a repositioned __syncthreads).
// smem: 70656 -> 53248 bytes  =>  4 CTAs/SM instead of <=3.
// ---------------------------------------------------------------------------
#define QP 68
#define VP 72

__global__ void __launch_bounds__(128, 4)
flash_attn_tf32(const float* __restrict__ qkv,
                const float* __restrict__ mask,
                float* __restrict__ out)
{
    extern __shared__ uint32_t sm[];
    uint32_t* Qs = sm;                  // [64][QP]  (persistent)
    uint32_t* Ks = sm + 64 * QP;        // [64][QP]  (doubles as P after S-phase)
    uint32_t* Vs = sm + 2 * 64 * QP;    // [64][VP]

    const int tid  = threadIdx.x;
    const int lane = tid & 31;
    const int wid  = tid >> 5;     // 0..3 -> q rows [wid*16, +16)
    const int g    = lane >> 2;    // 0..7
    const int tq   = lane & 3;     // 0..3

    const int q0 = blockIdx.x * 64;
    const int h  = blockIdx.y;
    const int b  = blockIdx.z;
    const float scale = 0.125f;

    const float* base = qkv + (size_t)b * Sq * (3 * Dq) + (size_t)h * (3 * HDq);

    // Load Q tile (64 x 64) as tf32
#pragma unroll
    for (int rr = 0; rr < 8; rr++) {
        const int r  = (tid >> 4) + rr * 8;
        const int c4 = (tid & 15) << 2;
        float4 v = *(const float4*)(base + (size_t)(q0 + r) * (3 * Dq) + c4);
        Qs[r * QP + c4 + 0] = f2tf32(v.x);
        Qs[r * QP + c4 + 1] = f2tf32(v.y);
        Qs[r * QP + c4 + 2] = f2tf32(v.z);
        Qs[r * QP + c4 + 3] = f2tf32(v.w);
    }

    float Oacc[8][4];
#pragma unroll
    for (int ni = 0; ni < 8; ni++)
#pragma unroll
        for (int e = 0; e < 4; e++) Oacc[ni][e] = 0.0f;
    float mrow0 = -INFINITY, mrow1 = -INFINITY;
    float lrow0 = 0.0f, lrow1 = 0.0f;

    const int r0 = wid * 16 + g;   // this thread's first q row (within tile)
    const int r1 = r0 + 8;

    for (int kt = 0; kt < Sq / 64; kt++) {
        const int k0t = kt * 64;
        __syncthreads();   // prev PV done reading Ks(P)/Vs; Q visible on 1st iter

        // Load K and V tiles
#pragma unroll
        for (int rr = 0; rr < 8; rr++) {
            const int r  = (tid >> 4) + rr * 8;
            const int c4 = (tid & 15) << 2;
            float4 kv = *(const float4*)(base + 64 + (size_t)(k0t + r) * (3 * Dq) + c4);
            Ks[r * QP + c4 + 0] = f2tf32(kv.x);
            Ks[r * QP + c4 + 1] = f2tf32(kv.y);
            Ks[r * QP + c4 + 2] = f2tf32(kv.z);
            Ks[r * QP + c4 + 3] = f2tf32(kv.w);
            float4 vv = *(const float4*)(base + 128 + (size_t)(k0t + r) * (3 * Dq) + c4);
            Vs[r * VP + c4 + 0] = f2tf32(vv.x);
            Vs[r * VP + c4 + 1] = f2tf32(vv.y);
            Vs[r * VP + c4 + 2] = f2tf32(vv.z);
            Vs[r * VP + c4 + 3] = f2tf32(vv.w);
        }
        __syncthreads();

        // S = Q K^T : warp computes 16 x 64 (8 n-tiles)
        float Sacc[8][4];
#pragma unroll
        for (int ni = 0; ni < 8; ni++)
#pragma unroll
            for (int e = 0; e < 4; e++) Sacc[ni][e] = 0.0f;

#pragma unroll
        for (int ks = 0; ks < 8; ks++) {
            const int kk = ks * 8;
            const int mb = wid * 16;
            uint32_t a0 = Qs[(mb + g)     * QP + kk + tq];
            uint32_t a1 = Qs[(mb + g + 8) * QP + kk + tq];
            uint32_t a2 = Qs[(mb + g)     * QP + kk + tq + 4];
            uint32_t a3 = Qs[(mb + g + 8) * QP + kk + tq + 4];
#pragma unroll
            for (int ni = 0; ni < 8; ni++) {
                const int nb = ni * 8;
                uint32_t b0 = Ks[(nb + g) * QP + kk + tq];
                uint32_t b1 = Ks[(nb + g) * QP + kk + tq + 4];
                mma_tf32(Sacc[ni], a0, a1, a2, a3, b0, b1);
            }
        }

        // scale + mask + online softmax (rows r0, r1; cols 8*ni + 2*tq {,+1})
        float p0[8][2], p1[8][2];
        float rmax0 = -INFINITY, rmax1 = -INFINITY;
#pragma unroll
        for (int ni = 0; ni < 8; ni++) {
            const int c = ni * 8 + 2 * tq;
            float2 mk0 = *(const float2*)(mask + (size_t)(q0 + r0) * Sq + k0t + c);
            float2 mk1 = *(const float2*)(mask + (size_t)(q0 + r1) * Sq + k0t + c);
            p0[ni][0] = Sacc[ni][0] * scale + mk0.x;
            p0[ni][1] = Sacc[ni][1] * scale + mk0.y;
            p1[ni][0] = Sacc[ni][2] * scale + mk1.x;
            p1[ni][1] = Sacc[ni][3] * scale + mk1.y;
            rmax0 = fmaxf(rmax0, fmaxf(p0[ni][0], p0[ni][1]));
            rmax1 = fmaxf(rmax1, fmaxf(p1[ni][0], p1[ni][1]));
        }
#pragma unroll
        for (int off = 1; off < 4; off <<= 1) {
            rmax0 = fmaxf(rmax0, __shfl_xor_sync(0xffffffffu, rmax0, off));
            rmax1 = fmaxf(rmax1, __shfl_xor_sync(0xffffffffu, rmax1, off));
        }
        const float mnew0 = fmaxf(mrow0, rmax0);
        const float mnew1 = fmaxf(mrow1, rmax1);
        const float alpha0 = __expf(mrow0 - mnew0);
        const float alpha1 = __expf(mrow1 - mnew1);
        float rs0 = 0.0f, rs1 = 0.0f;
#pragma unroll
        for (int ni = 0; ni < 8; ni++) {
            p0[ni][0] = __expf(p0[ni][0] - mnew0);
            p0[ni][1] = __expf(p0[ni][1] - mnew0);
            p1[ni][0] = __expf(p1[ni][0] - mnew1);
            p1[ni][1] = __expf(p1[ni][1] - mnew1);
            rs0 += p0[ni][0] + p0[ni][1];
            rs1 += p1[ni][0] + p1[ni][1];
        }
#pragma unroll
        for (int off = 1; off < 4; off <<= 1) {
            rs0 += __shfl_xor_sync(0xffffffffu, rs0, off);
            rs1 += __shfl_xor_sync(0xffffffffu, rs1, off);
        }
        lrow0 = lrow0 * alpha0 + rs0;
        lrow1 = lrow1 * alpha1 + rs1;
        mrow0 = mnew0;
        mrow1 = mnew1;
#pragma unroll
        for (int ni = 0; ni < 8; ni++) {
            Oacc[ni][0] *= alpha0; Oacc[ni][1] *= alpha0;
            Oacc[ni][2] *= alpha1; Oacc[ni][3] *= alpha1;
        }

        // All warps finished reading Ks in the S phase -> Ks reusable as P
        __syncthreads();

        // stash P (tf32) into this warp's private rows of Ks
        const int qr0 = wid * 16 + g;
#pragma unroll
        for (int ni = 0; ni < 8; ni++) {
            const int c = ni * 8 + 2 * tq;
            uint2 s0 = make_uint2(f2tf32(p0[ni][0]), f2tf32(p0[ni][1]));
            uint2 s1 = make_uint2(f2tf32(p1[ni][0]), f2tf32(p1[ni][1]));
            *(uint2*)(Ks + (qr0)     * QP + c) = s0;
            *(uint2*)(Ks + (qr0 + 8) * QP + c) = s1;
        }
        __syncwarp();

        // O += P V : A = Ks-as-P (16 x 64 keys), B = Vs (keys x hd)
#pragma unroll
        for (int ks = 0; ks < 8; ks++) {
            const int kk = ks * 8;
            const int mb = wid * 16;
            uint32_t a0 = Ks[(mb + g)     * QP + kk + tq];
            uint32_t a1 = Ks[(mb + g + 8) * QP + kk + tq];
            uint32_t a2 = Ks[(mb + g)     * QP + kk + tq + 4];
            uint32_t a3 = Ks[(mb + g + 8) * QP + kk + tq + 4];
#pragma unroll
            for (int ni = 0; ni < 8; ni++) {
                const int nb = ni * 8;
                uint32_t b0 = Vs[(kk + tq)     * VP + nb + g];
                uint32_t b1 = Vs[(kk + tq + 4) * VP + nb + g];
                mma_tf32(Oacc[ni], a0, a1, a2, a3, b0, b1);
            }
        }
    }

    // Epilogue
    const float inv0 = 1.0f / lrow0;
    const float inv1 = 1.0f / lrow1;
    float* obase = out + (size_t)b * Sq * Dq + (size_t)h * HDq;
#pragma unroll
    for (int ni = 0; ni < 8; ni++) {
        const int c = ni * 8 + 2 * tq;
        float2 o0 = make_float2(Oacc[ni][0] * inv0, Oacc[ni][1] * inv0);
        float2 o1 = make_float2(Oacc[ni][2] * inv1, Oacc[ni][3] * inv1);
        *(float2*)(obase + (size_t)(q0 + r0) * Dq + c) = o0;
        *(float2*)(obase + (size_t)(q0 + r1) * Dq + c) = o1;
    }
}

// ---------------------------------------------------------------------------
extern "C" void kernel_launch(void* const* d_in, const int* in_sizes, int n_in,
                              void* d_out, int out_size)
{
    const float* x    = (const float*)d_in[0];
    const float* mask = (const float*)d_in[1];
    const float* Wqkv = (const float*)d_in[2];
    const float* bqkv = (const float*)d_in[3];
    const float* Wo   = (const float*)d_in[4];
    const float* bo   = (const float*)d_in[5];
    float* out = (float*)d_out;

    float* qkv  = nullptr;
    float* vals = nullptr;
    cudaGetSymbolAddress((void**)&qkv,  g_qkv);
    cudaGetSymbolAddress((void**)&vals, g_vals);

    // 1) QKV projection
    {
        dim3 grid((3 * Dq) / 128, (Bq * Sq) / 128);
        gemm_tf32_nt_bias<<<grid, 256>>>(Bq * Sq, 3 * Dq, Dq, x, Wqkv, bqkv, qkv);
    }

    // 2) Flash attention (tf32 mma, 53KB smem -> 4 CTAs/SM)
    {
        const int smem = (2 * 64 * QP + 64 * VP) * (int)sizeof(uint32_t); // 53248 B
        cudaFuncSetAttribute(flash_attn_tf32,
                             cudaFuncAttributeMaxDynamicSharedMemorySize, smem);
        dim3 grid(Sq / 64, Hq, Bq);
        flash_attn_tf32<<<grid, 128, smem>>>(qkv, mask, vals);
    }

    // 3) Output projection
    {
        dim3 grid(Dq / 128, (Bq * Sq) / 128);
        gemm_tf32_nt_bias<<<grid, 256>>>(Bq * Sq, Dq, Dq, vals, Wo, bo, out);
    }
}